// round 1
// baseline (speedup 1.0000x reference)
#include <cuda_runtime.h>
#include <cuda_bf16.h>
#include <cstddef>

// ---------------- problem constants ----------------
#define BATCH   2
#define SEQL    1024
#define DIM_    1024
#define DSTATE  16
#define DCONV   4
#define DINNER  2048           // DIM * 2
#define MTOK    (BATCH*SEQL)   // 2048 token rows

// ---------------- scratch (static device globals; no allocation) ----------------
__device__ float g_xz   [ (size_t)MTOK * (2*DINNER) ];  // [M, 4096]
__device__ float g_xi   [ (size_t)MTOK * DINNER ];      // conv+silu output
__device__ float g_delta[ (size_t)MTOK * DINNER ];
__device__ float g_y    [ (size_t)MTOK * DINNER ];
__device__ float g_Bt   [ (size_t)MTOK * DSTATE ];
__device__ float g_Ct   [ (size_t)MTOK * DSTATE ];

// ---------------- SGEMM: C[M,N] = A[M,K] * B[N,K]^T (both K-major) ----------------
// EPI 0: plain store. EPI 1: softplus(acc + bias[n]). EPI 2: acc + res[m,n].
#define BM 128
#define BN 128
#define BK 8
#define TM 8
#define TN 8

__device__ __forceinline__ float softplus_f(float v) {
    return (v > 20.0f) ? v : log1pf(expf(v));
}

template <int EPI>
__global__ __launch_bounds__(256, 2)
void sgemm_nt(int M, int N, int K,
              const float* __restrict__ A,
              const float* __restrict__ B,
              float* __restrict__ C,
              const float* __restrict__ bias,
              const float* __restrict__ res)
{
    __shared__ float As[2][BK][BM];
    __shared__ float Bs[2][BK][BN];

    const int tid  = threadIdx.x;
    const int tRow = tid >> 4;          // 0..15
    const int tCol = tid & 15;          // 0..15

    const int ldRow = tid >> 1;         // 0..127
    const int ldCol = (tid & 1) * 4;    // 0 or 4

    const float* Ag = A + (size_t)blockIdx.y * BM * K + (size_t)ldRow * K + ldCol;
    const float* Bg = B + (size_t)blockIdx.x * BN * K + (size_t)ldRow * K + ldCol;

    float acc[TM][TN];
    #pragma unroll
    for (int i = 0; i < TM; i++)
        #pragma unroll
        for (int j = 0; j < TN; j++) acc[i][j] = 0.0f;

    const int nt = K / BK;

    // prefetch tile 0
    float4 a4 = *(const float4*)(Ag);
    float4 b4 = *(const float4*)(Bg);
    As[0][ldCol + 0][ldRow] = a4.x;
    As[0][ldCol + 1][ldRow] = a4.y;
    As[0][ldCol + 2][ldRow] = a4.z;
    As[0][ldCol + 3][ldRow] = a4.w;
    Bs[0][ldCol + 0][ldRow] = b4.x;
    Bs[0][ldCol + 1][ldRow] = b4.y;
    Bs[0][ldCol + 2][ldRow] = b4.z;
    Bs[0][ldCol + 3][ldRow] = b4.w;
    __syncthreads();

    int buf = 0;
    for (int t = 0; t < nt; t++) {
        if (t + 1 < nt) {
            a4 = *(const float4*)(Ag + (size_t)(t + 1) * BK);
            b4 = *(const float4*)(Bg + (size_t)(t + 1) * BK);
        }
        #pragma unroll
        for (int k = 0; k < BK; k++) {
            float rm[TM], rn[TN];
            #pragma unroll
            for (int i = 0; i < TM; i++) rm[i] = As[buf][k][tRow * TM + i];
            #pragma unroll
            for (int j = 0; j < TN; j++) rn[j] = Bs[buf][k][tCol * TN + j];
            #pragma unroll
            for (int i = 0; i < TM; i++)
                #pragma unroll
                for (int j = 0; j < TN; j++)
                    acc[i][j] = fmaf(rm[i], rn[j], acc[i][j]);
        }
        if (t + 1 < nt) {
            const int nb = buf ^ 1;
            As[nb][ldCol + 0][ldRow] = a4.x;
            As[nb][ldCol + 1][ldRow] = a4.y;
            As[nb][ldCol + 2][ldRow] = a4.z;
            As[nb][ldCol + 3][ldRow] = a4.w;
            Bs[nb][ldCol + 0][ldRow] = b4.x;
            Bs[nb][ldCol + 1][ldRow] = b4.y;
            Bs[nb][ldCol + 2][ldRow] = b4.z;
            Bs[nb][ldCol + 3][ldRow] = b4.w;
        }
        __syncthreads();
        buf ^= 1;
    }

    const int row0 = blockIdx.y * BM + tRow * TM;
    const int col0 = blockIdx.x * BN + tCol * TN;
    #pragma unroll
    for (int i = 0; i < TM; i++) {
        float v[TN];
        #pragma unroll
        for (int j = 0; j < TN; j++) {
            float a = acc[i][j];
            if (EPI == 1) a = softplus_f(a + bias[col0 + j]);
            if (EPI == 2) a = a + res[(size_t)(row0 + i) * N + col0 + j];
            v[j] = a;
        }
        float* Cp = C + (size_t)(row0 + i) * N + col0;
        *(float4*)(Cp)     = make_float4(v[0], v[1], v[2], v[3]);
        *(float4*)(Cp + 4) = make_float4(v[4], v[5], v[6], v[7]);
    }
}

// ---------------- causal depthwise conv (k=4) + bias + SiLU ----------------
__global__ void conv_silu_kernel(const float* __restrict__ Wc,
                                 const float* __restrict__ bc)
{
    const int idx = blockIdx.x * blockDim.x + threadIdx.x;   // over B*L*DINNER
    if (idx >= MTOK * DINNER) return;
    const int d = idx & (DINNER - 1);
    const int l = (idx >> 11) & (SEQL - 1);
    const int b = idx >> 21;

    float accv = bc[d];
    const float w0 = Wc[d * 4 + 0], w1 = Wc[d * 4 + 1],
                w2 = Wc[d * 4 + 2], w3 = Wc[d * 4 + 3];
    const size_t rowbase = ((size_t)b * SEQL) * (2 * DINNER) + d;
    if (l >= 3) accv += g_xz[rowbase + (size_t)(l - 3) * (2 * DINNER)] * w0;
    if (l >= 2) accv += g_xz[rowbase + (size_t)(l - 2) * (2 * DINNER)] * w1;
    if (l >= 1) accv += g_xz[rowbase + (size_t)(l - 1) * (2 * DINNER)] * w2;
    accv += g_xz[rowbase + (size_t)l * (2 * DINNER)] * w3;

    g_xi[idx] = accv / (1.0f + expf(-accv));   // silu
}

// ---------------- B_t / C_t projection: per-token dot products ----------------
__global__ void bc_kernel(const float* __restrict__ WB,
                          const float* __restrict__ WC)
{
    __shared__ float xs[DINNER];
    const int m = blockIdx.x;                       // token 0..2047
    const float4* row = (const float4*)(g_xi + (size_t)m * DINNER);
    for (int i = threadIdx.x; i < DINNER / 4; i += blockDim.x)
        ((float4*)xs)[i] = row[i];
    __syncthreads();

    const int warp = threadIdx.x >> 5;
    const int lane = threadIdx.x & 31;
    for (int so = 0; so < 8; so++) {
        const int s = warp * 8 + so;                // 0..31
        const float* w = (s < DSTATE) ? (WB + (size_t)s * DINNER)
                                      : (WC + (size_t)(s - DSTATE) * DINNER);
        float accv = 0.0f;
        for (int k = lane; k < DINNER; k += 32)
            accv = fmaf(xs[k], w[k], accv);
        #pragma unroll
        for (int off = 16; off; off >>= 1)
            accv += __shfl_xor_sync(0xffffffffu, accv, off);
        if (lane == 0) {
            if (s < DSTATE) g_Bt[(size_t)m * DSTATE + s] = accv;
            else            g_Ct[(size_t)m * DSTATE + (s - DSTATE)] = accv;
        }
    }
}

// ---------------- selective scan + D skip + SiLU(z) gating ----------------
// thread = (channel, state); 16 channels per 256-thread block; grid = 256 blocks
__global__ void scan_kernel(const float* __restrict__ A_log,
                            const float* __restrict__ Dv)
{
    const int tid = threadIdx.x;
    const int s   = tid & 15;
    const int chl = tid >> 4;                    // 0..15
    const int blk = blockIdx.x;                  // 0..255
    const int b   = blk >> 7;                    // 128 blocks per batch
    const int d   = (blk & 127) * 16 + chl;

    const float Asv = -expf(A_log[s]);
    const float Dd  = Dv[d];
    float h = 0.0f;

    size_t base   = ((size_t)b * SEQL) * DINNER + d;
    size_t bcbase = ((size_t)b * SEQL) * DSTATE + s;
    size_t zbase  = ((size_t)b * SEQL) * (2 * DINNER) + DINNER + d;

    for (int l = 0; l < SEQL; l++) {
        const float dv = g_delta[base];
        const float xv = g_xi[base];
        const float Bv = g_Bt[bcbase];
        const float Cv = g_Ct[bcbase];

        const float e = expf(dv * Asv);
        h = fmaf(h, e, dv * xv * Bv);

        float p = h * Cv;
        p += __shfl_xor_sync(0xffffffffu, p, 8);
        p += __shfl_xor_sync(0xffffffffu, p, 4);
        p += __shfl_xor_sync(0xffffffffu, p, 2);
        p += __shfl_xor_sync(0xffffffffu, p, 1);

        if (s == 0) {
            const float z  = g_xz[zbase];
            const float yv = (p + xv * Dd) * (z / (1.0f + expf(-z)));
            g_y[base] = yv;
        }
        base   += DINNER;
        bcbase += DSTATE;
        zbase  += 2 * DINNER;
    }
}

// ---------------- launcher ----------------
extern "C" void kernel_launch(void* const* d_in, const int* in_sizes, int n_in,
                              void* d_out, int out_size)
{
    const float* x      = (const float*)d_in[0];
    const float* W_in   = (const float*)d_in[1];
    const float* W_conv = (const float*)d_in[2];
    const float* b_conv = (const float*)d_in[3];
    const float* W_dt   = (const float*)d_in[4];
    const float* b_dt   = (const float*)d_in[5];
    const float* W_B    = (const float*)d_in[6];
    const float* W_C    = (const float*)d_in[7];
    const float* A_log  = (const float*)d_in[8];
    const float* Dvec   = (const float*)d_in[9];
    const float* W_out  = (const float*)d_in[10];
    float* out = (float*)d_out;

    float *p_xz, *p_xi, *p_delta, *p_y;
    cudaGetSymbolAddress((void**)&p_xz,    g_xz);
    cudaGetSymbolAddress((void**)&p_xi,    g_xi);
    cudaGetSymbolAddress((void**)&p_delta, g_delta);
    cudaGetSymbolAddress((void**)&p_y,     g_y);

    // 1) xz = x @ W_in^T          [2048,4096]
    {
        dim3 grid((2 * DINNER) / BN, MTOK / BM);
        sgemm_nt<0><<<grid, 256>>>(MTOK, 2 * DINNER, DIM_, x, W_in, p_xz, nullptr, nullptr);
    }
    // 2) causal conv + silu -> g_xi
    {
        const int n = MTOK * DINNER;
        conv_silu_kernel<<<(n + 255) / 256, 256>>>(W_conv, b_conv);
    }
    // 3) delta = softplus(xi @ W_dt^T + b_dt)
    {
        dim3 grid(DINNER / BN, MTOK / BM);
        sgemm_nt<1><<<grid, 256>>>(MTOK, DINNER, DINNER, p_xi, W_dt, p_delta, b_dt, nullptr);
    }
    // 4) B_t, C_t
    bc_kernel<<<MTOK, 128>>>(W_B, W_C);

    // 5) selective scan + gating -> g_y
    scan_kernel<<<(BATCH * DINNER) / 16, 256>>>(A_log, Dvec);

    // 6) out = x + y @ W_out^T
    {
        dim3 grid(DIM_ / BN, MTOK / BM);
        sgemm_nt<2><<<grid, 256>>>(MTOK, DIM_, DINNER, p_y, W_out, out, nullptr, x);
    }
}

// round 3
// speedup vs baseline: 1.4581x; 1.4581x over previous
#include <cuda_runtime.h>
#include <cuda_bf16.h>
#include <cstdint>
#include <cstddef>

// ---------------- problem constants ----------------
#define BATCH   2
#define SEQL    1024
#define DIM_    1024
#define DSTATE  16
#define DINNER  2048           // DIM * 2
#define MTOK    (BATCH*SEQL)   // 2048 token rows

// ---------------- scratch (static device globals; no allocation) ----------------
__device__ float g_xz   [ (size_t)MTOK * (2*DINNER) ];  // [M, 4096]
__device__ float g_xi   [ (size_t)MTOK * DINNER ];      // conv+silu output
__device__ float g_delta[ (size_t)MTOK * DINNER ];
__device__ float g_y    [ (size_t)MTOK * DINNER ];
__device__ float g_Bt   [ (size_t)MTOK * DSTATE ];
__device__ float g_Ct   [ (size_t)MTOK * DSTATE ];

// =====================================================================
//  helpers
// =====================================================================
__device__ __forceinline__ uint32_t smem_u32(const void* p) {
    uint32_t a;
    asm("{ .reg .u64 t; cvta.to.shared.u64 t, %1; cvt.u32.u64 %0, t; }"
        : "=r"(a) : "l"(p));
    return a;
}

// pack two fp32 into bf16x2 (lo = element k, hi = element k+1)
__device__ __forceinline__ uint32_t pack_bf16x2(float lo, float hi) {
    uint32_t d;
    asm("cvt.rn.bf16x2.f32 %0, %1, %2;" : "=r"(d) : "f"(hi), "f"(lo));
    return d;
}
__device__ __forceinline__ float bf16lo_f(uint32_t d) { return __uint_as_float(d << 16); }
__device__ __forceinline__ float bf16hi_f(uint32_t d) { return __uint_as_float(d & 0xffff0000u); }

__device__ __forceinline__ void sts_v2(uint32_t addr, uint32_t a, uint32_t b) {
    asm volatile("st.shared.v2.b32 [%0], {%1, %2};" :: "r"(addr), "r"(a), "r"(b) : "memory");
}

__device__ __forceinline__ void ldsm_x4(uint32_t addr, uint32_t r[4]) {
    asm volatile("ldmatrix.sync.aligned.m8n8.x4.shared.b16 {%0,%1,%2,%3}, [%4];"
                 : "=r"(r[0]), "=r"(r[1]), "=r"(r[2]), "=r"(r[3]) : "r"(addr));
}
__device__ __forceinline__ void ldsm_x2(uint32_t addr, uint32_t r[2]) {
    asm volatile("ldmatrix.sync.aligned.m8n8.x2.shared.b16 {%0,%1}, [%2];"
                 : "=r"(r[0]), "=r"(r[1]) : "r"(addr));
}

__device__ __forceinline__ void mma_bf16(float c[4], const uint32_t a[4], const uint32_t b[2]) {
    asm volatile(
        "mma.sync.aligned.m16n8k16.row.col.f32.bf16.bf16.f32 "
        "{%0,%1,%2,%3}, {%4,%5,%6,%7}, {%8,%9}, {%0,%1,%2,%3};"
        : "+f"(c[0]), "+f"(c[1]), "+f"(c[2]), "+f"(c[3])
        : "r"(a[0]), "r"(a[1]), "r"(a[2]), "r"(a[3]), "r"(b[0]), "r"(b[1]));
}

__device__ __forceinline__ float softplus_f(float v) {
    return (v > 20.0f) ? v : log1pf(expf(v));
}

// =====================================================================
//  bf16x3 mma.sync GEMM:  C[M,N] = A[M,K] * B[N,K]^T  (both K-major fp32)
//  CTA tile 128x128, BK=32, 512 threads (warp grid 4x4, warp tile 32x32).
//  smem tiles (hi/lo for A and B): rows padded to 40 halves (80 B) so
//  ldmatrix phases hit all 32 banks.
//  EPI 0: plain.  EPI 1: softplus(acc + bias[n]).  EPI 2: acc + res[m,n].
// =====================================================================
#define ROWB        80u                 // bytes per smem row (32 halves + 8 pad)
#define TILEB       (128u * ROWB)       // 10240 B per matrix tile
#define OFF_AHI     0u
#define OFF_ALO     (TILEB)
#define OFF_BHI     (2u * TILEB)
#define OFF_BLO     (3u * TILEB)
#define STAGEB      (4u * TILEB)        // 40960
#define GSMEM       (2u * STAGEB)       // 81920

struct Pack8 {                          // 8 floats -> hi/lo bf16x2 quads
    uint32_t h[4], l[4];
};
__device__ __forceinline__ Pack8 split8(float4 v0, float4 v1) {
    Pack8 p;
    p.h[0] = pack_bf16x2(v0.x, v0.y);
    p.h[1] = pack_bf16x2(v0.z, v0.w);
    p.h[2] = pack_bf16x2(v1.x, v1.y);
    p.h[3] = pack_bf16x2(v1.z, v1.w);
    p.l[0] = pack_bf16x2(v0.x - bf16lo_f(p.h[0]), v0.y - bf16hi_f(p.h[0]));
    p.l[1] = pack_bf16x2(v0.z - bf16lo_f(p.h[1]), v0.w - bf16hi_f(p.h[1]));
    p.l[2] = pack_bf16x2(v1.x - bf16lo_f(p.h[2]), v1.y - bf16hi_f(p.h[2]));
    p.l[3] = pack_bf16x2(v1.z - bf16lo_f(p.h[3]), v1.w - bf16hi_f(p.h[3]));
    return p;
}

template <int EPI>
__global__ __launch_bounds__(512)
void mma_gemm(int M, int N, int K,
              const float* __restrict__ A,
              const float* __restrict__ B,
              float* __restrict__ C,
              const float* __restrict__ bias,
              const float* __restrict__ res)
{
    extern __shared__ char smem[];
    const uint32_t sb = smem_u32(smem);
    const int tid  = threadIdx.x;
    const int lane = tid & 31;
    const int wid  = tid >> 5;
    const int wm   = (wid & 3) * 32;    // warp row offset in tile
    const int wn   = (wid >> 2) * 32;   // warp col offset in tile

    // ------- loader mapping: thread -> (row 0..127, k-quarter 0..3)
    const int lr = tid >> 2;
    const int lq = tid & 3;
    const float* Ag = A + (size_t)(blockIdx.y * 128 + lr) * K + lq * 8;
    const float* Bg = B + (size_t)(blockIdx.x * 128 + lr) * K + lq * 8;
    const uint32_t stsA = (uint32_t)lr * ROWB + (uint32_t)lq * 16;   // byte off in tile

    // ------- ldmatrix per-lane address pieces
    const uint32_t a_row = (uint32_t)(wm + (lane & 15));
    const uint32_t a_kb  = (uint32_t)(lane >> 4);            // 0/1
    const uint32_t b_row = (uint32_t)(wn + (lane & 7));
    const uint32_t b_kb  = (uint32_t)((lane >> 3) & 1);      // 0/1 (lanes>=16 ignored)

    float acc[2][4][4];
    #pragma unroll
    for (int mi = 0; mi < 2; mi++)
        #pragma unroll
        for (int ni = 0; ni < 4; ni++)
            #pragma unroll
            for (int q = 0; q < 4; q++) acc[mi][ni][q] = 0.0f;

    const int nt = K / 32;

    // preload stage 0
    float4 va0 = *(const float4*)(Ag),     va1 = *(const float4*)(Ag + 4);
    float4 vb0 = *(const float4*)(Bg),     vb1 = *(const float4*)(Bg + 4);
    {
        Pack8 pa = split8(va0, va1);
        Pack8 pb = split8(vb0, vb1);
        const uint32_t st = sb;
        sts_v2(st + OFF_AHI + stsA,     pa.h[0], pa.h[1]);
        sts_v2(st + OFF_AHI + stsA + 8, pa.h[2], pa.h[3]);
        sts_v2(st + OFF_ALO + stsA,     pa.l[0], pa.l[1]);
        sts_v2(st + OFF_ALO + stsA + 8, pa.l[2], pa.l[3]);
        sts_v2(st + OFF_BHI + stsA,     pb.h[0], pb.h[1]);
        sts_v2(st + OFF_BHI + stsA + 8, pb.h[2], pb.h[3]);
        sts_v2(st + OFF_BLO + stsA,     pb.l[0], pb.l[1]);
        sts_v2(st + OFF_BLO + stsA + 8, pb.l[2], pb.l[3]);
    }
    __syncthreads();

    for (int t = 0; t < nt; t++) {
        if (t + 1 < nt) {
            const float* Ap = Ag + (size_t)(t + 1) * 32;
            const float* Bp = Bg + (size_t)(t + 1) * 32;
            va0 = *(const float4*)(Ap);     va1 = *(const float4*)(Ap + 4);
            vb0 = *(const float4*)(Bp);     vb1 = *(const float4*)(Bp + 4);
        }
        const uint32_t st = sb + (uint32_t)(t & 1) * STAGEB;

        #pragma unroll
        for (int ks = 0; ks < 2; ks++) {
            const uint32_t kbyteA = (uint32_t)(ks * 2 + a_kb) * 16;
            const uint32_t kbyteB = (uint32_t)(ks * 2 + b_kb) * 16;
            uint32_t ah[2][4], al[2][4], bh[4][2], bl[4][2];
            #pragma unroll
            for (int mi = 0; mi < 2; mi++)
                ldsm_x4(st + OFF_AHI + (a_row + mi * 16) * ROWB + kbyteA, ah[mi]);
            #pragma unroll
            for (int ni = 0; ni < 4; ni++)
                ldsm_x2(st + OFF_BHI + (b_row + ni * 8) * ROWB + kbyteB, bh[ni]);
            // hi*hi
            #pragma unroll
            for (int mi = 0; mi < 2; mi++)
                #pragma unroll
                for (int ni = 0; ni < 4; ni++)
                    mma_bf16(acc[mi][ni], ah[mi], bh[ni]);
            // hi*lo
            #pragma unroll
            for (int ni = 0; ni < 4; ni++)
                ldsm_x2(st + OFF_BLO + (b_row + ni * 8) * ROWB + kbyteB, bl[ni]);
            #pragma unroll
            for (int mi = 0; mi < 2; mi++)
                #pragma unroll
                for (int ni = 0; ni < 4; ni++)
                    mma_bf16(acc[mi][ni], ah[mi], bl[ni]);
            // lo*hi
            #pragma unroll
            for (int mi = 0; mi < 2; mi++)
                ldsm_x4(st + OFF_ALO + (a_row + mi * 16) * ROWB + kbyteA, al[mi]);
            #pragma unroll
            for (int mi = 0; mi < 2; mi++)
                #pragma unroll
                for (int ni = 0; ni < 4; ni++)
                    mma_bf16(acc[mi][ni], al[mi], bh[ni]);
        }

        if (t + 1 < nt) {
            Pack8 pa = split8(va0, va1);
            Pack8 pb = split8(vb0, vb1);
            const uint32_t sn = sb + (uint32_t)((t + 1) & 1) * STAGEB;
            sts_v2(sn + OFF_AHI + stsA,     pa.h[0], pa.h[1]);
            sts_v2(sn + OFF_AHI + stsA + 8, pa.h[2], pa.h[3]);
            sts_v2(sn + OFF_ALO + stsA,     pa.l[0], pa.l[1]);
            sts_v2(sn + OFF_ALO + stsA + 8, pa.l[2], pa.l[3]);
            sts_v2(sn + OFF_BHI + stsA,     pb.h[0], pb.h[1]);
            sts_v2(sn + OFF_BHI + stsA + 8, pb.h[2], pb.h[3]);
            sts_v2(sn + OFF_BLO + stsA,     pb.l[0], pb.l[1]);
            sts_v2(sn + OFF_BLO + stsA + 8, pb.l[2], pb.l[3]);
        }
        __syncthreads();
    }

    // ------- epilogue: fragment (gid, tig) mapping of m16n8 C tiles
    const int gid = lane >> 2;
    const int tig = lane & 3;
    #pragma unroll
    for (int mi = 0; mi < 2; mi++) {
        #pragma unroll
        for (int ni = 0; ni < 4; ni++) {
            const int row0 = blockIdx.y * 128 + wm + mi * 16 + gid;
            const int col  = blockIdx.x * 128 + wn + ni * 8 + tig * 2;
            float c0 = acc[mi][ni][0], c1 = acc[mi][ni][1];
            float c2 = acc[mi][ni][2], c3 = acc[mi][ni][3];
            if (EPI == 1) {
                c0 = softplus_f(c0 + bias[col]);     c1 = softplus_f(c1 + bias[col + 1]);
                c2 = softplus_f(c2 + bias[col]);     c3 = softplus_f(c3 + bias[col + 1]);
            }
            if (EPI == 2) {
                const float2 r0 = *(const float2*)(res + (size_t)row0 * N + col);
                const float2 r1 = *(const float2*)(res + (size_t)(row0 + 8) * N + col);
                c0 += r0.x; c1 += r0.y; c2 += r1.x; c3 += r1.y;
            }
            *(float2*)(C + (size_t)row0 * N + col)       = make_float2(c0, c1);
            *(float2*)(C + (size_t)(row0 + 8) * N + col) = make_float2(c2, c3);
        }
    }
}

// ---------------- causal depthwise conv (k=4) + bias + SiLU ----------------
__global__ void conv_silu_kernel(const float* __restrict__ Wc,
                                 const float* __restrict__ bc)
{
    const int idx = blockIdx.x * blockDim.x + threadIdx.x;   // over B*L*DINNER
    if (idx >= MTOK * DINNER) return;
    const int d = idx & (DINNER - 1);
    const int l = (idx >> 11) & (SEQL - 1);
    const int b = idx >> 21;

    float accv = bc[d];
    const float w0 = Wc[d * 4 + 0], w1 = Wc[d * 4 + 1],
                w2 = Wc[d * 4 + 2], w3 = Wc[d * 4 + 3];
    const size_t rowbase = ((size_t)b * SEQL) * (2 * DINNER) + d;
    if (l >= 3) accv += g_xz[rowbase + (size_t)(l - 3) * (2 * DINNER)] * w0;
    if (l >= 2) accv += g_xz[rowbase + (size_t)(l - 2) * (2 * DINNER)] * w1;
    if (l >= 1) accv += g_xz[rowbase + (size_t)(l - 1) * (2 * DINNER)] * w2;
    accv += g_xz[rowbase + (size_t)l * (2 * DINNER)] * w3;

    g_xi[idx] = accv / (1.0f + expf(-accv));   // silu
}

// ---------------- B_t / C_t projection: 4 tokens per block ----------------
__global__ void bc_kernel(const float* __restrict__ WB,
                          const float* __restrict__ WC)
{
    __shared__ float xs[4][DINNER];             // 32 KB
    const int m0 = blockIdx.x * 4;
    for (int t4 = 0; t4 < 4; t4++) {
        const float4* row = (const float4*)(g_xi + (size_t)(m0 + t4) * DINNER);
        for (int i = threadIdx.x; i < DINNER / 4; i += blockDim.x)
            ((float4*)xs[t4])[i] = row[i];
    }
    __syncthreads();

    const int warp = threadIdx.x >> 5;
    const int lane = threadIdx.x & 31;
    for (int so = 0; so < 8; so++) {
        const int s = warp * 8 + so;            // 0..31
        const float* w = (s < DSTATE) ? (WB + (size_t)s * DINNER)
                                      : (WC + (size_t)(s - DSTATE) * DINNER);
        float a0 = 0.f, a1 = 0.f, a2 = 0.f, a3 = 0.f;
        for (int k = lane; k < DINNER; k += 32) {
            const float wv = w[k];
            a0 = fmaf(xs[0][k], wv, a0);
            a1 = fmaf(xs[1][k], wv, a1);
            a2 = fmaf(xs[2][k], wv, a2);
            a3 = fmaf(xs[3][k], wv, a3);
        }
        #pragma unroll
        for (int off = 16; off; off >>= 1) {
            a0 += __shfl_xor_sync(0xffffffffu, a0, off);
            a1 += __shfl_xor_sync(0xffffffffu, a1, off);
            a2 += __shfl_xor_sync(0xffffffffu, a2, off);
            a3 += __shfl_xor_sync(0xffffffffu, a3, off);
        }
        if (lane == 0) {
            float* dst = (s < DSTATE) ? g_Bt : g_Ct;
            const int sc = (s < DSTATE) ? s : (s - DSTATE);
            dst[(size_t)(m0 + 0) * DSTATE + sc] = a0;
            dst[(size_t)(m0 + 1) * DSTATE + sc] = a1;
            dst[(size_t)(m0 + 2) * DSTATE + sc] = a2;
            dst[(size_t)(m0 + 3) * DSTATE + sc] = a3;
        }
    }
}

// ---------------- selective scan + D skip + SiLU(z) gating ----------------
__global__ void scan_kernel(const float* __restrict__ A_log,
                            const float* __restrict__ Dv)
{
    const int tid = threadIdx.x;
    const int s   = tid & 15;
    const int chl = tid >> 4;                    // 0..15
    const int blk = blockIdx.x;                  // 0..255
    const int b   = blk >> 7;                    // 128 blocks per batch
    const int d   = (blk & 127) * 16 + chl;

    const float Asv = -expf(A_log[s]);
    const float Dd  = Dv[d];
    float h = 0.0f;

    size_t base   = ((size_t)b * SEQL) * DINNER + d;
    size_t bcbase = ((size_t)b * SEQL) * DSTATE + s;
    size_t zbase  = ((size_t)b * SEQL) * (2 * DINNER) + DINNER + d;

    for (int l = 0; l < SEQL; l++) {
        const float dv = g_delta[base];
        const float xv = g_xi[base];
        const float Bv = g_Bt[bcbase];
        const float Cv = g_Ct[bcbase];

        const float e = expf(dv * Asv);
        h = fmaf(h, e, dv * xv * Bv);

        float p = h * Cv;
        p += __shfl_xor_sync(0xffffffffu, p, 8);
        p += __shfl_xor_sync(0xffffffffu, p, 4);
        p += __shfl_xor_sync(0xffffffffu, p, 2);
        p += __shfl_xor_sync(0xffffffffu, p, 1);

        if (s == 0) {
            const float z  = g_xz[zbase];
            const float yv = (p + xv * Dd) * (z / (1.0f + expf(-z)));
            g_y[base] = yv;
        }
        base   += DINNER;
        bcbase += DSTATE;
        zbase  += 2 * DINNER;
    }
}

// ---------------- launcher ----------------
extern "C" void kernel_launch(void* const* d_in, const int* in_sizes, int n_in,
                              void* d_out, int out_size)
{
    const float* x      = (const float*)d_in[0];
    const float* W_in   = (const float*)d_in[1];
    const float* W_conv = (const float*)d_in[2];
    const float* b_conv = (const float*)d_in[3];
    const float* W_dt   = (const float*)d_in[4];
    const float* b_dt   = (const float*)d_in[5];
    const float* W_B    = (const float*)d_in[6];
    const float* W_C    = (const float*)d_in[7];
    const float* A_log  = (const float*)d_in[8];
    const float* Dvec   = (const float*)d_in[9];
    const float* W_out  = (const float*)d_in[10];
    float* out = (float*)d_out;

    float *p_xz, *p_xi, *p_delta, *p_y;
    cudaGetSymbolAddress((void**)&p_xz,    g_xz);
    cudaGetSymbolAddress((void**)&p_xi,    g_xi);
    cudaGetSymbolAddress((void**)&p_delta, g_delta);
    cudaGetSymbolAddress((void**)&p_y,     g_y);

    static bool attr_done = false;
    if (!attr_done) {
        cudaFuncSetAttribute(mma_gemm<0>, cudaFuncAttributeMaxDynamicSharedMemorySize, GSMEM);
        cudaFuncSetAttribute(mma_gemm<1>, cudaFuncAttributeMaxDynamicSharedMemorySize, GSMEM);
        cudaFuncSetAttribute(mma_gemm<2>, cudaFuncAttributeMaxDynamicSharedMemorySize, GSMEM);
        attr_done = true;
    }

    // 1) xz = x @ W_in^T          [2048, 4096]
    {
        dim3 grid((2 * DINNER) / 128, MTOK / 128);
        mma_gemm<0><<<grid, 512, GSMEM>>>(MTOK, 2 * DINNER, DIM_,
                                          x, W_in, p_xz, nullptr, nullptr);
    }
    // 2) causal conv + silu -> g_xi
    {
        const int n = MTOK * DINNER;
        conv_silu_kernel<<<(n + 255) / 256, 256>>>(W_conv, b_conv);
    }
    // 3) delta = softplus(xi @ W_dt^T + b_dt)   [2048, 2048]
    {
        dim3 grid(DINNER / 128, MTOK / 128);
        mma_gemm<1><<<grid, 512, GSMEM>>>(MTOK, DINNER, DINNER,
                                          p_xi, W_dt, p_delta, b_dt, nullptr);
    }
    // 4) B_t, C_t
    bc_kernel<<<MTOK / 4, 128>>>(W_B, W_C);

    // 5) selective scan + gating -> g_y
    scan_kernel<<<(BATCH * DINNER) / 16, 256>>>(A_log, Dvec);

    // 6) out = x + y @ W_out^T    [2048, 1024]
    {
        dim3 grid(DIM_ / 128, MTOK / 128);
        mma_gemm<2><<<grid, 512, GSMEM>>>(MTOK, DIM_, DINNER,
                                          p_y, W_out, out, nullptr, x);
    }
}